// round 11
// baseline (speedup 1.0000x reference)
#include <cuda_runtime.h>
#include <cuda_bf16.h>
#include <cuda_fp16.h>
#include <cstdint>

#define N_NODES 100000
#define N_EDGES 1600000
#define D_IN    256
#define D_OUT   64
#define BN_EPS  1e-5f
#define CAP     80      // per-node adjacency capacity (Poisson(16): P(deg>=80)<1e-30)

// Scratch (device globals — no allocation allowed)
// g_yh has one extra all-zero row (index N_NODES) used as padding target.
__device__ __half2 g_yh[((size_t)N_NODES + 1) * 32];  // dinv-scaled x W^T (after k_scale)
__device__ int     g_cnt[N_NODES];                    // degree / fill cursor
__device__ float   g_dinv[N_NODES];
__device__ int     g_adj[(size_t)N_NODES * CAP];      // bucketed adjacency

// ---------------------------------------------------------------------------
// Adjacency build: one edge pass into fixed-capacity buckets.
// ---------------------------------------------------------------------------
__global__ __launch_bounds__(256) void k_fill4(const int4* __restrict__ rows4,
                                               const int4* __restrict__ cols4) {
    int i = blockIdx.x * blockDim.x + threadIdx.x;
    if (i < N_EDGES / 4) {
        int4 r = rows4[i];
        int4 c = cols4[i];
        int p0 = atomicAdd(&g_cnt[c.x], 1);
        int p1 = atomicAdd(&g_cnt[c.y], 1);
        int p2 = atomicAdd(&g_cnt[c.z], 1);
        int p3 = atomicAdd(&g_cnt[c.w], 1);
        g_adj[(size_t)c.x * CAP + p0] = r.x;
        g_adj[(size_t)c.y * CAP + p1] = r.y;
        g_adj[(size_t)c.z * CAP + p2] = r.z;
        g_adj[(size_t)c.w * CAP + p3] = r.w;
    }
}
// dinv + pad adjacency to multiple of 4 with dummy zero-row index + zero row
__global__ void k_dinv() {
    int i = blockIdx.x * blockDim.x + threadIdx.x;
    if (i < 8) *(uint4*)&g_yh[(size_t)N_NODES * 32 + i * 4] = make_uint4(0, 0, 0, 0);
    if (i < N_NODES) {
        int d = g_cnt[i];
        g_dinv[i] = rsqrtf((float)(d + 1));   // +1 self-loop
        int pad = (4 - (d & 3)) & 3;
        #pragma unroll
        for (int p = 0; p < 3; p++)
            if (p < pad) g_adj[(size_t)i * CAP + d + p] = N_NODES;
    }
}

// ---------------------------------------------------------------------------
// Tensor-core GEMM via mma.sync, software-pipelined. y = x W^T (unscaled),
// split-bf16 (hi*hi + hi*lo + lo*hi), fp32 accum, half2 store.
// ---------------------------------------------------------------------------
#define ROWB 144
static constexpr int SM_XHI = 0;
static constexpr int SM_XLO = SM_XHI + 128 * ROWB;
static constexpr int SM_WHI = SM_XLO + 128 * ROWB;
static constexpr int SM_WLO = SM_WHI + 64 * ROWB;
static constexpr int SM_TOTAL = SM_WLO + 64 * ROWB;  // 55296

__device__ __forceinline__ void mma_bf16(float* c, const uint32_t* a,
                                         uint32_t b0, uint32_t b1) {
    asm volatile(
        "mma.sync.aligned.m16n8k16.row.col.f32.bf16.bf16.f32 "
        "{%0,%1,%2,%3}, {%4,%5,%6,%7}, {%8,%9}, {%0,%1,%2,%3};"
        : "+f"(c[0]), "+f"(c[1]), "+f"(c[2]), "+f"(c[3])
        : "r"(a[0]), "r"(a[1]), "r"(a[2]), "r"(a[3]), "r"(b0), "r"(b1));
}
__device__ __forceinline__ uint32_t lds_u32(const char* base, int off) {
    return *(const uint32_t*)(base + off);
}

__device__ __forceinline__ void load_chunk_regs(const float* __restrict__ x,
                                                const float* __restrict__ Wp,
                                                int nodeBase, int kc, int tid,
                                                float4* xv, float4* wv) {
    #pragma unroll
    for (int i = 0; i < 8; i++) {
        int idx = tid + 256 * i;
        int row = idx >> 4, g = idx & 15;
        int node = nodeBase + row;
        xv[i] = (node < N_NODES)
              ? *(const float4*)&x[(size_t)node * D_IN + kc + g * 4]
              : make_float4(0.f, 0.f, 0.f, 0.f);
    }
    #pragma unroll
    for (int i = 0; i < 4; i++) {
        int idx = tid + 256 * i;
        int row = idx >> 4, g = idx & 15;
        wv[i] = *(const float4*)&Wp[(size_t)row * D_IN + kc + g * 4];
    }
}

__device__ __forceinline__ void store_chunk_smem(char* sm, int tid,
                                                 const float4* xv, const float4* wv) {
    #pragma unroll
    for (int i = 0; i < 8; i++) {
        int idx = tid + 256 * i;
        int row = idx >> 4, g = idx & 15;
        float f[4] = {xv[i].x, xv[i].y, xv[i].z, xv[i].w};
        __nv_bfloat16 hi[4], lo[4];
        #pragma unroll
        for (int j = 0; j < 4; j++) {
            hi[j] = __float2bfloat16(f[j]);
            lo[j] = __float2bfloat16(f[j] - __bfloat162float(hi[j]));
        }
        int off = row * ROWB + g * 8;
        *(uint2*)(sm + SM_XHI + off) = *(uint2*)hi;
        *(uint2*)(sm + SM_XLO + off) = *(uint2*)lo;
    }
    #pragma unroll
    for (int i = 0; i < 4; i++) {
        int idx = tid + 256 * i;
        int row = idx >> 4, g = idx & 15;
        float f[4] = {wv[i].x, wv[i].y, wv[i].z, wv[i].w};
        __nv_bfloat16 hi[4], lo[4];
        #pragma unroll
        for (int j = 0; j < 4; j++) {
            hi[j] = __float2bfloat16(f[j]);
            lo[j] = __float2bfloat16(f[j] - __bfloat162float(hi[j]));
        }
        int off = row * ROWB + g * 8;
        *(uint2*)(sm + SM_WHI + off) = *(uint2*)hi;
        *(uint2*)(sm + SM_WLO + off) = *(uint2*)lo;
    }
}

__global__ __launch_bounds__(256) void k_gemm_mma(const float* __restrict__ x,
                                                  const float* __restrict__ Wp) {
    extern __shared__ char sm[];
    const int tid = threadIdx.x;
    const int w   = tid >> 5;
    const int lane = tid & 31;
    const int nodeBase = blockIdx.x * 128;

    float acc[8][4];
    #pragma unroll
    for (int nt = 0; nt < 8; nt++)
        #pragma unroll
        for (int j = 0; j < 4; j++) acc[nt][j] = 0.f;

    float4 xv[8], wv[4];
    load_chunk_regs(x, Wp, nodeBase, 0, tid, xv, wv);
    store_chunk_smem(sm, tid, xv, wv);
    __syncthreads();

    for (int c = 0; c < 4; c++) {
        if (c < 3) load_chunk_regs(x, Wp, nodeBase, (c + 1) * 64, tid, xv, wv);

        #pragma unroll
        for (int ks = 0; ks < 4; ks++) {
            const int kb = ks * 32 + (lane & 3) * 4;
            const int ar = (w * 16 + (lane >> 2)) * ROWB;
            uint32_t ah[4], al[4];
            ah[0] = lds_u32(sm + SM_XHI, ar + kb);
            ah[1] = lds_u32(sm + SM_XHI, ar + 8 * ROWB + kb);
            ah[2] = lds_u32(sm + SM_XHI, ar + kb + 16);
            ah[3] = lds_u32(sm + SM_XHI, ar + 8 * ROWB + kb + 16);
            al[0] = lds_u32(sm + SM_XLO, ar + kb);
            al[1] = lds_u32(sm + SM_XLO, ar + 8 * ROWB + kb);
            al[2] = lds_u32(sm + SM_XLO, ar + kb + 16);
            al[3] = lds_u32(sm + SM_XLO, ar + 8 * ROWB + kb + 16);

            #pragma unroll
            for (int nt = 0; nt < 8; nt++) {
                const int br = (nt * 8 + (lane >> 2)) * ROWB;
                uint32_t bh0 = lds_u32(sm + SM_WHI, br + kb);
                uint32_t bh1 = lds_u32(sm + SM_WHI, br + kb + 16);
                uint32_t bl0 = lds_u32(sm + SM_WLO, br + kb);
                uint32_t bl1 = lds_u32(sm + SM_WLO, br + kb + 16);
                mma_bf16(acc[nt], ah, bh0, bh1);
                mma_bf16(acc[nt], ah, bl0, bl1);
                mma_bf16(acc[nt], al, bh0, bh1);
            }
        }
        __syncthreads();
        if (c < 3) {
            store_chunk_smem(sm, tid, xv, wv);
            __syncthreads();
        }
    }

    // store as half2: col pair (nt*8 + (lane&3)*2, +1) -> index nt*4 + (lane&3)
    const int r0 = nodeBase + w * 16 + (lane >> 2);
    const int r1 = r0 + 8;
    #pragma unroll
    for (int nt = 0; nt < 8; nt++) {
        const int pj = nt * 4 + (lane & 3);
        if (r0 < N_NODES)
            g_yh[(size_t)r0 * 32 + pj] = __floats2half2_rn(acc[nt][0], acc[nt][1]);
        if (r1 < N_NODES)
            g_yh[(size_t)r1 * 32 + pj] = __floats2half2_rn(acc[nt][2], acc[nt][3]);
    }
}

// ---------------------------------------------------------------------------
// Scale: g_yh[node] *= dinv[node] (in place). Runs after join (needs both).
// ---------------------------------------------------------------------------
__global__ __launch_bounds__(256) void k_scale() {
    int i = blockIdx.x * blockDim.x + threadIdx.x;   // one uint2 = 2 half2
    if (i < N_NODES * 16) {
        float di = g_dinv[i >> 4];
        __half2* p = &g_yh[(size_t)i * 2];
        float2 a = __half22float2(p[0]);
        float2 b = __half22float2(p[1]);
        p[0] = __floats2half2_rn(a.x * di, a.y * di);
        p[1] = __floats2half2_rn(b.x * di, b.y * di);
    }
}

// ---------------------------------------------------------------------------
// Gather: one warp per node. 8 lanes per row (uint4 each), 4 neighbors per
// iteration, single variable-src shuffle. Butterfly-reduce over the 4 groups.
// ---------------------------------------------------------------------------
__device__ __forceinline__ void acc_u4(float* acc, uint4 v) {
    float2 f0 = __half22float2(*reinterpret_cast<const __half2*>(&v.x));
    float2 f1 = __half22float2(*reinterpret_cast<const __half2*>(&v.y));
    float2 f2 = __half22float2(*reinterpret_cast<const __half2*>(&v.z));
    float2 f3 = __half22float2(*reinterpret_cast<const __half2*>(&v.w));
    acc[0] += f0.x; acc[1] += f0.y; acc[2] += f1.x; acc[3] += f1.y;
    acc[4] += f2.x; acc[5] += f2.y; acc[6] += f3.x; acc[7] += f3.y;
}

__global__ __launch_bounds__(256) void k_gather(const float* __restrict__ bias,
                                                const float* __restrict__ gamma,
                                                const float* __restrict__ beta,
                                                const float* __restrict__ mean,
                                                const float* __restrict__ var,
                                                float* __restrict__ out) {
    const int warp = (blockIdx.x * blockDim.x + threadIdx.x) >> 5;
    const int lane = threadIdx.x & 31;
    if (warp >= N_NODES) return;
    const int node = warp;
    const int lq = lane & 7;    // column group: cols [lq*8, lq*8+8)
    const int lg = lane >> 3;   // neighbor subgroup 0..3

    float acc[8] = {0.f, 0.f, 0.f, 0.f, 0.f, 0.f, 0.f, 0.f};

    // self term (scaled row), group 0 only
    if (lg == 0)
        acc_u4(acc, *(const uint4*)&g_yh[(size_t)node * 32 + lq * 4]);

    const int deg  = g_cnt[node];
    const int degp = (deg + 3) & ~3;
    const size_t s = (size_t)node * CAP;

    for (int base = 0; base < degp; base += 32) {
        int r = N_NODES;
        if (base + lane < degp) r = g_adj[s + base + lane];
        const int cnt = min(32, degp - base);   // multiple of 4
        for (int j = 0; j < cnt; j += 4) {
            int rr = __shfl_sync(0xffffffffu, r, j + lg);
            uint4 v = *(const uint4*)&g_yh[(size_t)rr * 32 + lq * 4];
            acc_u4(acc, v);
        }
    }

    // reduce across the 4 neighbor subgroups (lanes lq, lq+8, lq+16, lq+24)
    #pragma unroll
    for (int t = 0; t < 8; t++) {
        acc[t] += __shfl_xor_sync(0xffffffffu, acc[t], 8);
        acc[t] += __shfl_xor_sync(0xffffffffu, acc[t], 16);
    }

    if (lg == 0) {
        const int c0 = lq * 8;
        const float di = g_dinv[node];
        float o[8];
        #pragma unroll
        for (int t = 0; t < 8; t++) {
            int d = c0 + t;
            float sc = rsqrtf(var[d] + BN_EPS) * gamma[d];
            o[t] = fmaxf((acc[t] * di + bias[d] - mean[d]) * sc + beta[d], 0.f);
        }
        *(float4*)&out[(size_t)node * D_OUT + c0]     = make_float4(o[0], o[1], o[2], o[3]);
        *(float4*)&out[(size_t)node * D_OUT + c0 + 4] = make_float4(o[4], o[5], o[6], o[7]);
    }
}

// ---------------------------------------------------------------------------
extern "C" void kernel_launch(void* const* d_in, const int* in_sizes, int n_in,
                              void* d_out, int out_size) {
    const float* x     = (const float*)d_in[0];
    const int*   ei    = (const int*)  d_in[1];
    const float* W     = (const float*)d_in[2];
    const float* bias  = (const float*)d_in[3];
    const float* gamma = (const float*)d_in[4];
    const float* beta  = (const float*)d_in[5];
    const float* mean  = (const float*)d_in[6];
    const float* var   = (const float*)d_in[7];
    float* out = (float*)d_out;

    const int4* rows4 = (const int4*)ei;              // edge_index[0] = source
    const int4* cols4 = (const int4*)(ei + N_EDGES);  // edge_index[1] = target

    static cudaStream_t s2 = nullptr;
    static cudaEvent_t evFork = nullptr, evJoin = nullptr;
    static void* cnt_addr = nullptr;
    if (!s2) {
        cudaStreamCreateWithFlags(&s2, cudaStreamNonBlocking);
        cudaEventCreateWithFlags(&evFork, cudaEventDisableTiming);
        cudaEventCreateWithFlags(&evJoin, cudaEventDisableTiming);
        cudaGetSymbolAddress(&cnt_addr, g_cnt);
        cudaFuncSetAttribute(k_gemm_mma, cudaFuncAttributeMaxDynamicSharedMemorySize, SM_TOTAL);
    }

    // fork: adjacency build on s2, GEMM on the capture (default) stream
    cudaEventRecord(evFork, 0);
    cudaStreamWaitEvent(s2, evFork, 0);

    cudaMemsetAsync(cnt_addr, 0, N_NODES * sizeof(int), s2);
    k_fill4<<<(N_EDGES / 4 + 255) / 256, 256, 0, s2>>>(rows4, cols4);
    k_dinv <<<(N_NODES + 255) / 256, 256, 0, s2>>>();

    k_gemm_mma<<<(N_NODES + 127) / 128, 256, SM_TOTAL>>>(x, W);

    // join
    cudaEventRecord(evJoin, s2);
    cudaStreamWaitEvent(0, evJoin, 0);

    k_scale <<<(N_NODES * 16 + 255) / 256, 256>>>();
    k_gather<<<(N_NODES * 32 + 255) / 256, 256>>>(bias, gamma, beta, mean, var, out);
}

// round 12
// speedup vs baseline: 1.0631x; 1.0631x over previous
#include <cuda_runtime.h>
#include <cuda_bf16.h>
#include <cuda_fp16.h>
#include <cstdint>

#define N_NODES 100000
#define N_EDGES 1600000
#define D_IN    256
#define D_OUT   64
#define BN_EPS  1e-5f
#define CAP     88      // 80 (Poisson(16) bound) + 7 padding slots
#define ROWBYTES 128    // one y row = 64 half = 128 B
#define ZOFF    (N_NODES * ROWBYTES)   // byte offset of the zero row

// Scratch (device globals — no allocation allowed)
__device__ __half2 g_yh[((size_t)N_NODES + 1) * 32];  // dinv-scaled x W^T + zero row
__device__ int     g_cnt[N_NODES];                    // in-degree (count branch)
__device__ int     g_cur[N_NODES];                    // fill cursors (fill branch)
__device__ float   g_dinv[N_NODES];
__device__ int     g_adj[(size_t)N_NODES * CAP];      // BYTE OFFSETS of source rows

// ---------------------------------------------------------------------------
// Main-stream prefix: degree count + dinv (feeds the GEMM epilogue)
// ---------------------------------------------------------------------------
__global__ __launch_bounds__(256) void k_count4(const int4* __restrict__ cols4) {
    int i = blockIdx.x * blockDim.x + threadIdx.x;
    if (i < N_EDGES / 4) {
        int4 c = cols4[i];
        atomicAdd(&g_cnt[c.x], 1);
        atomicAdd(&g_cnt[c.y], 1);
        atomicAdd(&g_cnt[c.z], 1);
        atomicAdd(&g_cnt[c.w], 1);
    }
}
__global__ void k_dinv() {
    int i = blockIdx.x * blockDim.x + threadIdx.x;
    if (i < N_NODES) g_dinv[i] = rsqrtf((float)(g_cnt[i] + 1));   // +1 self-loop
}

// ---------------------------------------------------------------------------
// s2 branch: adjacency fill (byte offsets) + padding to multiple of 8
// ---------------------------------------------------------------------------
__global__ __launch_bounds__(256) void k_fill4(const int4* __restrict__ rows4,
                                               const int4* __restrict__ cols4) {
    int i = blockIdx.x * blockDim.x + threadIdx.x;
    if (i < N_EDGES / 4) {
        int4 r = rows4[i];
        int4 c = cols4[i];
        int p0 = atomicAdd(&g_cur[c.x], 1);
        int p1 = atomicAdd(&g_cur[c.y], 1);
        int p2 = atomicAdd(&g_cur[c.z], 1);
        int p3 = atomicAdd(&g_cur[c.w], 1);
        g_adj[(size_t)c.x * CAP + p0] = r.x << 7;   // byte offset = r * 128
        g_adj[(size_t)c.y * CAP + p1] = r.y << 7;
        g_adj[(size_t)c.z * CAP + p2] = r.z << 7;
        g_adj[(size_t)c.w * CAP + p3] = r.w << 7;
    }
}
__global__ void k_pad() {
    int i = blockIdx.x * blockDim.x + threadIdx.x;
    if (i < 32) g_yh[(size_t)N_NODES * 32 + i] = __floats2half2_rn(0.f, 0.f);
    if (i < N_NODES) {
        int d = g_cur[i];
        int degp = (d + 7) & ~7;
        for (int p = d; p < degp; p++) g_adj[(size_t)i * CAP + p] = ZOFF;
    }
}

// ---------------------------------------------------------------------------
// Tensor-core GEMM via mma.sync, software-pipelined. Stores dinv-scaled half2.
// split-bf16 (hi*hi + hi*lo + lo*hi), fp32 accum. CTA: 128 nodes x 64 douts.
// ---------------------------------------------------------------------------
#define ROWB 144
static constexpr int SM_XHI = 0;
static constexpr int SM_XLO = SM_XHI + 128 * ROWB;
static constexpr int SM_WHI = SM_XLO + 128 * ROWB;
static constexpr int SM_WLO = SM_WHI + 64 * ROWB;
static constexpr int SM_TOTAL = SM_WLO + 64 * ROWB;  // 55296

__device__ __forceinline__ void mma_bf16(float* c, const uint32_t* a,
                                         uint32_t b0, uint32_t b1) {
    asm volatile(
        "mma.sync.aligned.m16n8k16.row.col.f32.bf16.bf16.f32 "
        "{%0,%1,%2,%3}, {%4,%5,%6,%7}, {%8,%9}, {%0,%1,%2,%3};"
        : "+f"(c[0]), "+f"(c[1]), "+f"(c[2]), "+f"(c[3])
        : "r"(a[0]), "r"(a[1]), "r"(a[2]), "r"(a[3]), "r"(b0), "r"(b1));
}
__device__ __forceinline__ uint32_t lds_u32(const char* base, int off) {
    return *(const uint32_t*)(base + off);
}

__device__ __forceinline__ void load_chunk_regs(const float* __restrict__ x,
                                                const float* __restrict__ Wp,
                                                int nodeBase, int kc, int tid,
                                                float4* xv, float4* wv) {
    #pragma unroll
    for (int i = 0; i < 8; i++) {
        int idx = tid + 256 * i;
        int row = idx >> 4, g = idx & 15;
        int node = nodeBase + row;
        xv[i] = (node < N_NODES)
              ? *(const float4*)&x[(size_t)node * D_IN + kc + g * 4]
              : make_float4(0.f, 0.f, 0.f, 0.f);
    }
    #pragma unroll
    for (int i = 0; i < 4; i++) {
        int idx = tid + 256 * i;
        int row = idx >> 4, g = idx & 15;
        wv[i] = *(const float4*)&Wp[(size_t)row * D_IN + kc + g * 4];
    }
}

__device__ __forceinline__ void store_chunk_smem(char* sm, int tid,
                                                 const float4* xv, const float4* wv) {
    #pragma unroll
    for (int i = 0; i < 8; i++) {
        int idx = tid + 256 * i;
        int row = idx >> 4, g = idx & 15;
        float f[4] = {xv[i].x, xv[i].y, xv[i].z, xv[i].w};
        __nv_bfloat16 hi[4], lo[4];
        #pragma unroll
        for (int j = 0; j < 4; j++) {
            hi[j] = __float2bfloat16(f[j]);
            lo[j] = __float2bfloat16(f[j] - __bfloat162float(hi[j]));
        }
        int off = row * ROWB + g * 8;
        *(uint2*)(sm + SM_XHI + off) = *(uint2*)hi;
        *(uint2*)(sm + SM_XLO + off) = *(uint2*)lo;
    }
    #pragma unroll
    for (int i = 0; i < 4; i++) {
        int idx = tid + 256 * i;
        int row = idx >> 4, g = idx & 15;
        float f[4] = {wv[i].x, wv[i].y, wv[i].z, wv[i].w};
        __nv_bfloat16 hi[4], lo[4];
        #pragma unroll
        for (int j = 0; j < 4; j++) {
            hi[j] = __float2bfloat16(f[j]);
            lo[j] = __float2bfloat16(f[j] - __bfloat162float(hi[j]));
        }
        int off = row * ROWB + g * 8;
        *(uint2*)(sm + SM_WHI + off) = *(uint2*)hi;
        *(uint2*)(sm + SM_WLO + off) = *(uint2*)lo;
    }
}

__global__ __launch_bounds__(256) void k_gemm_mma(const float* __restrict__ x,
                                                  const float* __restrict__ Wp) {
    extern __shared__ char sm[];
    const int tid = threadIdx.x;
    const int w   = tid >> 5;
    const int lane = tid & 31;
    const int nodeBase = blockIdx.x * 128;

    float acc[8][4];
    #pragma unroll
    for (int nt = 0; nt < 8; nt++)
        #pragma unroll
        for (int j = 0; j < 4; j++) acc[nt][j] = 0.f;

    float4 xv[8], wv[4];
    load_chunk_regs(x, Wp, nodeBase, 0, tid, xv, wv);
    store_chunk_smem(sm, tid, xv, wv);
    __syncthreads();

    for (int c = 0; c < 4; c++) {
        if (c < 3) load_chunk_regs(x, Wp, nodeBase, (c + 1) * 64, tid, xv, wv);

        #pragma unroll
        for (int ks = 0; ks < 4; ks++) {
            const int kb = ks * 32 + (lane & 3) * 4;
            const int ar = (w * 16 + (lane >> 2)) * ROWB;
            uint32_t ah[4], al[4];
            ah[0] = lds_u32(sm + SM_XHI, ar + kb);
            ah[1] = lds_u32(sm + SM_XHI, ar + 8 * ROWB + kb);
            ah[2] = lds_u32(sm + SM_XHI, ar + kb + 16);
            ah[3] = lds_u32(sm + SM_XHI, ar + 8 * ROWB + kb + 16);
            al[0] = lds_u32(sm + SM_XLO, ar + kb);
            al[1] = lds_u32(sm + SM_XLO, ar + 8 * ROWB + kb);
            al[2] = lds_u32(sm + SM_XLO, ar + kb + 16);
            al[3] = lds_u32(sm + SM_XLO, ar + 8 * ROWB + kb + 16);

            #pragma unroll
            for (int nt = 0; nt < 8; nt++) {
                const int br = (nt * 8 + (lane >> 2)) * ROWB;
                uint32_t bh0 = lds_u32(sm + SM_WHI, br + kb);
                uint32_t bh1 = lds_u32(sm + SM_WHI, br + kb + 16);
                uint32_t bl0 = lds_u32(sm + SM_WLO, br + kb);
                uint32_t bl1 = lds_u32(sm + SM_WLO, br + kb + 16);
                mma_bf16(acc[nt], ah, bh0, bh1);
                mma_bf16(acc[nt], ah, bl0, bl1);
                mma_bf16(acc[nt], al, bh0, bh1);
            }
        }
        __syncthreads();
        if (c < 3) {
            store_chunk_smem(sm, tid, xv, wv);
            __syncthreads();
        }
    }

    // store dinv-scaled half2 (dinv ready: k_dinv precedes on this stream)
    const int r0 = nodeBase + w * 16 + (lane >> 2);
    const int r1 = r0 + 8;
    const float di0 = (r0 < N_NODES) ? g_dinv[r0] : 0.f;
    const float di1 = (r1 < N_NODES) ? g_dinv[r1] : 0.f;
    #pragma unroll
    for (int nt = 0; nt < 8; nt++) {
        const int pj = nt * 4 + (lane & 3);
        if (r0 < N_NODES)
            g_yh[(size_t)r0 * 32 + pj] = __floats2half2_rn(acc[nt][0] * di0, acc[nt][1] * di0);
        if (r1 < N_NODES)
            g_yh[(size_t)r1 * 32 + pj] = __floats2half2_rn(acc[nt][2] * di1, acc[nt][3] * di1);
    }
}

// ---------------------------------------------------------------------------
// Gather: one warp per node. y pre-scaled by dinv; adjacency holds byte
// offsets; inner loop tail-free (×8 pad) and unrolled 8-wide for MLP.
// out = relu((dinv[n]*(y[n]+Σy[r]) + bias - mean)*rsqrt(var+eps)*gamma + beta)
// ---------------------------------------------------------------------------
__global__ __launch_bounds__(256) void k_gather(const float* __restrict__ bias,
                                                const float* __restrict__ gamma,
                                                const float* __restrict__ beta,
                                                const float* __restrict__ mean,
                                                const float* __restrict__ var,
                                                float* __restrict__ out) {
    const int warp = (blockIdx.x * blockDim.x + threadIdx.x) >> 5;
    const int lane = threadIdx.x & 31;
    if (warp >= N_NODES) return;
    const int node = warp;
    const int c0 = lane * 2;

    const char* yb = (const char*)g_yh + c0 * 2;   // this lane's column pair

    float2 sv = __half22float2(g_yh[(size_t)node * 32 + lane]);
    float2 acc = make_float2(sv.x, sv.y);          // self term (pre-scaled)

    const int deg  = g_cur[node];
    const int degp = (deg + 7) & ~7;
    const size_t s = (size_t)node * CAP;

    for (int base = 0; base < degp; base += 32) {
        int off = ZOFF;
        if (base + lane < degp) off = g_adj[s + base + lane];
        const int cnt = min(32, degp - base);      // multiple of 8
        for (int j = 0; j < cnt; j += 8) {
            int o0 = __shfl_sync(0xffffffffu, off, j + 0);
            int o1 = __shfl_sync(0xffffffffu, off, j + 1);
            int o2 = __shfl_sync(0xffffffffu, off, j + 2);
            int o3 = __shfl_sync(0xffffffffu, off, j + 3);
            int o4 = __shfl_sync(0xffffffffu, off, j + 4);
            int o5 = __shfl_sync(0xffffffffu, off, j + 5);
            int o6 = __shfl_sync(0xffffffffu, off, j + 6);
            int o7 = __shfl_sync(0xffffffffu, off, j + 7);
            __half2 v0 = *(const __half2*)(yb + o0);
            __half2 v1 = *(const __half2*)(yb + o1);
            __half2 v2 = *(const __half2*)(yb + o2);
            __half2 v3 = *(const __half2*)(yb + o3);
            __half2 v4 = *(const __half2*)(yb + o4);
            __half2 v5 = *(const __half2*)(yb + o5);
            __half2 v6 = *(const __half2*)(yb + o6);
            __half2 v7 = *(const __half2*)(yb + o7);
            float2 f0 = __half22float2(v0), f1 = __half22float2(v1);
            float2 f2 = __half22float2(v2), f3 = __half22float2(v3);
            float2 f4 = __half22float2(v4), f5 = __half22float2(v5);
            float2 f6 = __half22float2(v6), f7 = __half22float2(v7);
            acc.x += (f0.x + f1.x) + (f2.x + f3.x) + (f4.x + f5.x) + (f6.x + f7.x);
            acc.y += (f0.y + f1.y) + (f2.y + f3.y) + (f4.y + f5.y) + (f6.y + f7.y);
        }
    }

    const float di = g_dinv[node];
    float sc0 = rsqrtf(var[c0] + BN_EPS) * gamma[c0];
    float sc1 = rsqrtf(var[c0 + 1] + BN_EPS) * gamma[c0 + 1];
    float2 o;
    o.x = fmaxf((acc.x * di + bias[c0]     - mean[c0])     * sc0 + beta[c0],     0.f);
    o.y = fmaxf((acc.y * di + bias[c0 + 1] - mean[c0 + 1]) * sc1 + beta[c0 + 1], 0.f);
    *(float2*)&out[(size_t)node * D_OUT + c0] = o;
}

// ---------------------------------------------------------------------------
extern "C" void kernel_launch(void* const* d_in, const int* in_sizes, int n_in,
                              void* d_out, int out_size) {
    const float* x     = (const float*)d_in[0];
    const int*   ei    = (const int*)  d_in[1];
    const float* W     = (const float*)d_in[2];
    const float* bias  = (const float*)d_in[3];
    const float* gamma = (const float*)d_in[4];
    const float* beta  = (const float*)d_in[5];
    const float* mean  = (const float*)d_in[6];
    const float* var   = (const float*)d_in[7];
    float* out = (float*)d_out;

    const int4* rows4 = (const int4*)ei;              // edge_index[0] = source
    const int4* cols4 = (const int4*)(ei + N_EDGES);  // edge_index[1] = target

    static cudaStream_t s2 = nullptr;
    static cudaEvent_t evFork = nullptr, evJoin = nullptr;
    static void* cnt_addr = nullptr;
    static void* cur_addr = nullptr;
    if (!s2) {
        cudaStreamCreateWithFlags(&s2, cudaStreamNonBlocking);
        cudaEventCreateWithFlags(&evFork, cudaEventDisableTiming);
        cudaEventCreateWithFlags(&evJoin, cudaEventDisableTiming);
        cudaGetSymbolAddress(&cnt_addr, g_cnt);
        cudaGetSymbolAddress(&cur_addr, g_cur);
        cudaFuncSetAttribute(k_gemm_mma, cudaFuncAttributeMaxDynamicSharedMemorySize, SM_TOTAL);
    }

    // fork: adjacency fill+pad on s2; count+dinv+GEMM on main
    cudaEventRecord(evFork, 0);
    cudaStreamWaitEvent(s2, evFork, 0);

    cudaMemsetAsync(cur_addr, 0, N_NODES * sizeof(int), s2);
    k_fill4<<<(N_EDGES / 4 + 255) / 256, 256, 0, s2>>>(rows4, cols4);
    k_pad  <<<(N_NODES + 255) / 256, 256, 0, s2>>>();

    cudaMemsetAsync(cnt_addr, 0, N_NODES * sizeof(int), 0);
    k_count4<<<(N_EDGES / 4 + 255) / 256, 256>>>(cols4);
    k_dinv  <<<(N_NODES + 255) / 256, 256>>>();
    k_gemm_mma<<<(N_NODES + 127) / 128, 256, SM_TOTAL>>>(x, W);

    // join
    cudaEventRecord(evJoin, s2);
    cudaStreamWaitEvent(0, evJoin, 0);

    k_gather<<<(N_NODES * 32 + 255) / 256, 256>>>(bias, gamma, beta, mean, var, out);
}

// round 15
// speedup vs baseline: 1.1320x; 1.0649x over previous
#include <cuda_runtime.h>
#include <cuda_bf16.h>
#include <cuda_fp16.h>
#include <cstdint>

#define N_NODES 100000
#define N_EDGES 1600000
#define D_IN    256
#define D_OUT   64
#define BN_EPS  1e-5f
#define CAP     88      // 80 (Poisson(16) bound) + 7 padding slots
#define ROWBYTES 128    // one y row = 64 half = 128 B
#define ZOFF    (N_NODES * ROWBYTES)   // byte offset of the zero row

// Scratch (device globals — no allocation allowed)
__device__ __half2 g_yh[((size_t)N_NODES + 1) * 32];  // UNscaled x W^T + zero row
__device__ int     g_cur[N_NODES];                    // fill cursors -> degrees
__device__ float   g_dinv[N_NODES + 1];               // [N_NODES] = 0 (pad slot)
__device__ int     g_adj[(size_t)N_NODES * CAP];      // BYTE OFFSETS of source rows

// ---------------------------------------------------------------------------
// s2 branch: adjacency fill (byte offsets); degrees = final cursors;
// then dinv + pad-to-x8 + zero row in one pass.
// ---------------------------------------------------------------------------
__global__ __launch_bounds__(256) void k_fill4(const int4* __restrict__ rows4,
                                               const int4* __restrict__ cols4) {
    int i = blockIdx.x * blockDim.x + threadIdx.x;
    if (i < N_EDGES / 4) {
        int4 r = rows4[i];
        int4 c = cols4[i];
        int p0 = atomicAdd(&g_cur[c.x], 1);
        int p1 = atomicAdd(&g_cur[c.y], 1);
        int p2 = atomicAdd(&g_cur[c.z], 1);
        int p3 = atomicAdd(&g_cur[c.w], 1);
        g_adj[(size_t)c.x * CAP + p0] = r.x << 7;   // byte offset = r * 128
        g_adj[(size_t)c.y * CAP + p1] = r.y << 7;
        g_adj[(size_t)c.z * CAP + p2] = r.z << 7;
        g_adj[(size_t)c.w * CAP + p3] = r.w << 7;
    }
}
__global__ void k_dinvpad() {
    int i = blockIdx.x * blockDim.x + threadIdx.x;
    if (i < 32) g_yh[(size_t)N_NODES * 32 + i] = __floats2half2_rn(0.f, 0.f);
    if (i == 0) g_dinv[N_NODES] = 0.f;               // pad rows contribute 0
    if (i < N_NODES) {
        int d = g_cur[i];
        g_dinv[i] = rsqrtf((float)(d + 1));          // +1 self-loop
        int degp = (d + 7) & ~7;
        for (int p = d; p < degp; p++) g_adj[(size_t)i * CAP + p] = ZOFF;
    }
}

// ---------------------------------------------------------------------------
// Tensor-core GEMM via mma.sync, software-pipelined. Stores UNscaled half2.
// split-bf16 (hi*hi + hi*lo + lo*hi), fp32 accum. CTA: 128 nodes x 64 douts.
// No dependence on the graph branch at all.
// ---------------------------------------------------------------------------
#define ROWB 144
static constexpr int SM_XHI = 0;
static constexpr int SM_XLO = SM_XHI + 128 * ROWB;
static constexpr int SM_WHI = SM_XLO + 128 * ROWB;
static constexpr int SM_WLO = SM_WHI + 64 * ROWB;
static constexpr int SM_TOTAL = SM_WLO + 64 * ROWB;  // 55296

__device__ __forceinline__ void mma_bf16(float* c, const uint32_t* a,
                                         uint32_t b0, uint32_t b1) {
    asm volatile(
        "mma.sync.aligned.m16n8k16.row.col.f32.bf16.bf16.f32 "
        "{%0,%1,%2,%3}, {%4,%5,%6,%7}, {%8,%9}, {%0,%1,%2,%3};"
        : "+f"(c[0]), "+f"(c[1]), "+f"(c[2]), "+f"(c[3])
        : "r"(a[0]), "r"(a[1]), "r"(a[2]), "r"(a[3]), "r"(b0), "r"(b1));
}
__device__ __forceinline__ uint32_t lds_u32(const char* base, int off) {
    return *(const uint32_t*)(base + off);
}

__device__ __forceinline__ void load_chunk_regs(const float* __restrict__ x,
                                                const float* __restrict__ Wp,
                                                int nodeBase, int kc, int tid,
                                                float4* xv, float4* wv) {
    #pragma unroll
    for (int i = 0; i < 8; i++) {
        int idx = tid + 256 * i;
        int row = idx >> 4, g = idx & 15;
        int node = nodeBase + row;
        xv[i] = (node < N_NODES)
              ? *(const float4*)&x[(size_t)node * D_IN + kc + g * 4]
              : make_float4(0.f, 0.f, 0.f, 0.f);
    }
    #pragma unroll
    for (int i = 0; i < 4; i++) {
        int idx = tid + 256 * i;
        int row = idx >> 4, g = idx & 15;
        wv[i] = *(const float4*)&Wp[(size_t)row * D_IN + kc + g * 4];
    }
}

__device__ __forceinline__ void store_chunk_smem(char* sm, int tid,
                                                 const float4* xv, const float4* wv) {
    #pragma unroll
    for (int i = 0; i < 8; i++) {
        int idx = tid + 256 * i;
        int row = idx >> 4, g = idx & 15;
        float f[4] = {xv[i].x, xv[i].y, xv[i].z, xv[i].w};
        __nv_bfloat16 hi[4], lo[4];
        #pragma unroll
        for (int j = 0; j < 4; j++) {
            hi[j] = __float2bfloat16(f[j]);
            lo[j] = __float2bfloat16(f[j] - __bfloat162float(hi[j]));
        }
        int off = row * ROWB + g * 8;
        *(uint2*)(sm + SM_XHI + off) = *(uint2*)hi;
        *(uint2*)(sm + SM_XLO + off) = *(uint2*)lo;
    }
    #pragma unroll
    for (int i = 0; i < 4; i++) {
        int idx = tid + 256 * i;
        int row = idx >> 4, g = idx & 15;
        float f[4] = {wv[i].x, wv[i].y, wv[i].z, wv[i].w};
        __nv_bfloat16 hi[4], lo[4];
        #pragma unroll
        for (int j = 0; j < 4; j++) {
            hi[j] = __float2bfloat16(f[j]);
            lo[j] = __float2bfloat16(f[j] - __bfloat162float(hi[j]));
        }
        int off = row * ROWB + g * 8;
        *(uint2*)(sm + SM_WHI + off) = *(uint2*)hi;
        *(uint2*)(sm + SM_WLO + off) = *(uint2*)lo;
    }
}

__global__ __launch_bounds__(256) void k_gemm_mma(const float* __restrict__ x,
                                                  const float* __restrict__ Wp) {
    extern __shared__ char sm[];
    const int tid = threadIdx.x;
    const int w   = tid >> 5;
    const int lane = tid & 31;
    const int nodeBase = blockIdx.x * 128;

    float acc[8][4];
    #pragma unroll
    for (int nt = 0; nt < 8; nt++)
        #pragma unroll
        for (int j = 0; j < 4; j++) acc[nt][j] = 0.f;

    float4 xv[8], wv[4];
    load_chunk_regs(x, Wp, nodeBase, 0, tid, xv, wv);
    store_chunk_smem(sm, tid, xv, wv);
    __syncthreads();

    for (int c = 0; c < 4; c++) {
        if (c < 3) load_chunk_regs(x, Wp, nodeBase, (c + 1) * 64, tid, xv, wv);

        #pragma unroll
        for (int ks = 0; ks < 4; ks++) {
            const int kb = ks * 32 + (lane & 3) * 4;
            const int ar = (w * 16 + (lane >> 2)) * ROWB;
            uint32_t ah[4], al[4];
            ah[0] = lds_u32(sm + SM_XHI, ar + kb);
            ah[1] = lds_u32(sm + SM_XHI, ar + 8 * ROWB + kb);
            ah[2] = lds_u32(sm + SM_XHI, ar + kb + 16);
            ah[3] = lds_u32(sm + SM_XHI, ar + 8 * ROWB + kb + 16);
            al[0] = lds_u32(sm + SM_XLO, ar + kb);
            al[1] = lds_u32(sm + SM_XLO, ar + 8 * ROWB + kb);
            al[2] = lds_u32(sm + SM_XLO, ar + kb + 16);
            al[3] = lds_u32(sm + SM_XLO, ar + 8 * ROWB + kb + 16);

            #pragma unroll
            for (int nt = 0; nt < 8; nt++) {
                const int br = (nt * 8 + (lane >> 2)) * ROWB;
                uint32_t bh0 = lds_u32(sm + SM_WHI, br + kb);
                uint32_t bh1 = lds_u32(sm + SM_WHI, br + kb + 16);
                uint32_t bl0 = lds_u32(sm + SM_WLO, br + kb);
                uint32_t bl1 = lds_u32(sm + SM_WLO, br + kb + 16);
                mma_bf16(acc[nt], ah, bh0, bh1);
                mma_bf16(acc[nt], ah, bl0, bl1);
                mma_bf16(acc[nt], al, bh0, bh1);
            }
        }
        __syncthreads();
        if (c < 3) {
            store_chunk_smem(sm, tid, xv, wv);
            __syncthreads();
        }
    }

    // store UNscaled half2: col pair (nt*8 + (lane&3)*2, +1) -> pair idx nt*4+(lane&3)
    const int r0 = nodeBase + w * 16 + (lane >> 2);
    const int r1 = r0 + 8;
    #pragma unroll
    for (int nt = 0; nt < 8; nt++) {
        const int pj = nt * 4 + (lane & 3);
        if (r0 < N_NODES)
            g_yh[(size_t)r0 * 32 + pj] = __floats2half2_rn(acc[nt][0], acc[nt][1]);
        if (r1 < N_NODES)
            g_yh[(size_t)r1 * 32 + pj] = __floats2half2_rn(acc[nt][2], acc[nt][3]);
    }
}

// ---------------------------------------------------------------------------
// Gather: one warp per node. Per neighbor: 1 shuffle of its byte offset,
// one warp-uniform broadcast load of dinv[r], one half2 row load per lane.
// acc = dinv[n]*y[n] + Σ dinv[r]*y[r];  out = BN(acc*dinv[n]) -> relu
// ---------------------------------------------------------------------------
__global__ __launch_bounds__(256) void k_gather(const float* __restrict__ bias,
                                                const float* __restrict__ gamma,
                                                const float* __restrict__ beta,
                                                const float* __restrict__ mean,
                                                const float* __restrict__ var,
                                                float* __restrict__ out) {
    const int warp = (blockIdx.x * blockDim.x + threadIdx.x) >> 5;
    const int lane = threadIdx.x & 31;
    if (warp >= N_NODES) return;
    const int node = warp;
    const int c0 = lane * 2;

    const char* yb = (const char*)g_yh + c0 * 2;   // this lane's column pair

    const float di = g_dinv[node];
    float2 sv = __half22float2(g_yh[(size_t)node * 32 + lane]);
    float2 acc = make_float2(sv.x * di, sv.y * di); // self term

    const int deg  = g_cur[node];
    const int degp = (deg + 7) & ~7;
    const size_t s = (size_t)node * CAP;

    for (int base = 0; base < degp; base += 32) {
        int off = ZOFF;
        if (base + lane < degp) off = g_adj[s + base + lane];
        const int cnt = min(32, degp - base);      // multiple of 8
        for (int j = 0; j < cnt; j += 8) {
            int o0 = __shfl_sync(0xffffffffu, off, j + 0);
            int o1 = __shfl_sync(0xffffffffu, off, j + 1);
            int o2 = __shfl_sync(0xffffffffu, off, j + 2);
            int o3 = __shfl_sync(0xffffffffu, off, j + 3);
            int o4 = __shfl_sync(0xffffffffu, off, j + 4);
            int o5 = __shfl_sync(0xffffffffu, off, j + 5);
            int o6 = __shfl_sync(0xffffffffu, off, j + 6);
            int o7 = __shfl_sync(0xffffffffu, off, j + 7);
            // warp-uniform broadcast loads (ZOFF>>7 = N_NODES -> dinv 0)
            float d0 = g_dinv[o0 >> 7], d1 = g_dinv[o1 >> 7];
            float d2 = g_dinv[o2 >> 7], d3 = g_dinv[o3 >> 7];
            float d4 = g_dinv[o4 >> 7], d5 = g_dinv[o5 >> 7];
            float d6 = g_dinv[o6 >> 7], d7 = g_dinv[o7 >> 7];
            __half2 v0 = *(const __half2*)(yb + o0);
            __half2 v1 = *(const __half2*)(yb + o1);
            __half2 v2 = *(const __half2*)(yb + o2);
            __half2 v3 = *(const __half2*)(yb + o3);
            __half2 v4 = *(const __half2*)(yb + o4);
            __half2 v5 = *(const __half2*)(yb + o5);
            __half2 v6 = *(const __half2*)(yb + o6);
            __half2 v7 = *(const __half2*)(yb + o7);
            float2 f0 = __half22float2(v0), f1 = __half22float2(v1);
            float2 f2 = __half22float2(v2), f3 = __half22float2(v3);
            float2 f4 = __half22float2(v4), f5 = __half22float2(v5);
            float2 f6 = __half22float2(v6), f7 = __half22float2(v7);
            acc.x += d0 * f0.x + d1 * f1.x + d2 * f2.x + d3 * f3.x
                   + d4 * f4.x + d5 * f5.x + d6 * f6.x + d7 * f7.x;
            acc.y += d0 * f0.y + d1 * f1.y + d2 * f2.y + d3 * f3.y
                   + d4 * f4.y + d5 * f5.y + d6 * f6.y + d7 * f7.y;
        }
    }

    float sc0 = rsqrtf(var[c0] + BN_EPS) * gamma[c0];
    float sc1 = rsqrtf(var[c0 + 1] + BN_EPS) * gamma[c0 + 1];
    float2 o;
    o.x = fmaxf((acc.x * di + bias[c0]     - mean[c0])     * sc0 + beta[c0],     0.f);
    o.y = fmaxf((acc.y * di + bias[c0 + 1] - mean[c0 + 1]) * sc1 + beta[c0 + 1], 0.f);
    *(float2*)&out[(size_t)node * D_OUT + c0] = o;
}

// ---------------------------------------------------------------------------
extern "C" void kernel_launch(void* const* d_in, const int* in_sizes, int n_in,
                              void* d_out, int out_size) {
    const float* x     = (const float*)d_in[0];
    const int*   ei    = (const int*)  d_in[1];
    const float* W     = (const float*)d_in[2];
    const float* bias  = (const float*)d_in[3];
    const float* gamma = (const float*)d_in[4];
    const float* beta  = (const float*)d_in[5];
    const float* mean  = (const float*)d_in[6];
    const float* var   = (const float*)d_in[7];
    float* out = (float*)d_out;

    const int4* rows4 = (const int4*)ei;              // edge_index[0] = source
    const int4* cols4 = (const int4*)(ei + N_EDGES);  // edge_index[1] = target

    static cudaStream_t s2 = nullptr;
    static cudaEvent_t evFork = nullptr, evJoin = nullptr;
    static void* cur_addr = nullptr;
    if (!s2) {
        cudaStreamCreateWithFlags(&s2, cudaStreamNonBlocking);
        cudaEventCreateWithFlags(&evFork, cudaEventDisableTiming);
        cudaEventCreateWithFlags(&evJoin, cudaEventDisableTiming);
        cudaGetSymbolAddress(&cur_addr, g_cur);
        cudaFuncSetAttribute(k_gemm_mma, cudaFuncAttributeMaxDynamicSharedMemorySize, SM_TOTAL);
    }

    // fork: graph build on s2; GEMM (independent) on main
    cudaEventRecord(evFork, 0);
    cudaStreamWaitEvent(s2, evFork, 0);

    cudaMemsetAsync(cur_addr, 0, N_NODES * sizeof(int), s2);
    k_fill4  <<<(N_EDGES / 4 + 255) / 256, 256, 0, s2>>>(rows4, cols4);
    k_dinvpad<<<(N_NODES + 255) / 256, 256, 0, s2>>>();

    k_gemm_mma<<<(N_NODES + 127) / 128, 256, SM_TOTAL>>>(x, W);

    // join
    cudaEventRecord(evJoin, s2);
    cudaStreamWaitEvent(0, evJoin, 0);

    k_gather<<<(N_NODES * 32 + 255) / 256, 256>>>(bias, gamma, beta, mean, var, out);
}

// round 16
// speedup vs baseline: 1.2105x; 1.0694x over previous
#include <cuda_runtime.h>
#include <cuda_bf16.h>
#include <cuda_fp16.h>
#include <cstdint>

#define N_NODES 100000
#define N_EDGES 1600000
#define D_IN    256
#define D_OUT   64
#define BN_EPS  1e-5f
#define CAP     88      // 80 (Poisson(16) bound) + 3 padding slots
#define ROWBYTES 128    // one y row = 64 half = 128 B
#define ZOFF    (N_NODES * ROWBYTES)   // byte offset of the zero row

// Scratch (device globals — no allocation allowed)
__device__ __half2 g_yh[((size_t)N_NODES + 1) * 32];  // UNscaled x W^T + zero row
__device__ int     g_cur[N_NODES];                    // fill cursors -> degrees
__device__ float   g_dinv[N_NODES + 1];               // [N_NODES] = 0 (pad slot)
__device__ int     g_adj[(size_t)N_NODES * CAP];      // BYTE OFFSETS of source rows
__device__ float   g_sc[D_OUT];                       // rsqrt(var+eps)*gamma
__device__ float   g_sh[D_OUT];                       // (bias-mean)*sc + beta

// ---------------------------------------------------------------------------
// s2 branch: adjacency fill (byte offsets); degrees = final cursors;
// dinv + pad-to-x4 + zero row; BN constant folding.
// ---------------------------------------------------------------------------
__global__ __launch_bounds__(256) void k_fill4(const int4* __restrict__ rows4,
                                               const int4* __restrict__ cols4) {
    int i = blockIdx.x * blockDim.x + threadIdx.x;
    if (i < N_EDGES / 4) {
        int4 r = rows4[i];
        int4 c = cols4[i];
        int p0 = atomicAdd(&g_cur[c.x], 1);
        int p1 = atomicAdd(&g_cur[c.y], 1);
        int p2 = atomicAdd(&g_cur[c.z], 1);
        int p3 = atomicAdd(&g_cur[c.w], 1);
        g_adj[(size_t)c.x * CAP + p0] = r.x << 7;   // byte offset = r * 128
        g_adj[(size_t)c.y * CAP + p1] = r.y << 7;
        g_adj[(size_t)c.z * CAP + p2] = r.z << 7;
        g_adj[(size_t)c.w * CAP + p3] = r.w << 7;
    }
}
__global__ void k_dinvpad() {
    int i = blockIdx.x * blockDim.x + threadIdx.x;
    if (i < 32) g_yh[(size_t)N_NODES * 32 + i] = __floats2half2_rn(0.f, 0.f);
    if (i == 0) g_dinv[N_NODES] = 0.f;               // pad rows contribute 0
    if (i < N_NODES) {
        int d = g_cur[i];
        g_dinv[i] = rsqrtf((float)(d + 1));          // +1 self-loop
        int degp = (d + 3) & ~3;
        #pragma unroll
        for (int p = 0; p < 3; p++)
            if (d + p < degp) g_adj[(size_t)i * CAP + d + p] = ZOFF;
    }
}
__global__ void k_prep(const float* __restrict__ bias,
                       const float* __restrict__ gamma,
                       const float* __restrict__ beta,
                       const float* __restrict__ mean,
                       const float* __restrict__ var) {
    int d = threadIdx.x;
    if (d < D_OUT) {
        float sc = rsqrtf(var[d] + BN_EPS) * gamma[d];
        g_sc[d] = sc;
        g_sh[d] = (bias[d] - mean[d]) * sc + beta[d];
    }
}

// ---------------------------------------------------------------------------
// Tensor-core GEMM via mma.sync, software-pipelined. Stores UNscaled half2.
// split-bf16 (hi*hi + hi*lo + lo*hi), fp32 accum. CTA: 128 nodes x 64 douts.
// ---------------------------------------------------------------------------
#define ROWB 144
static constexpr int SM_XHI = 0;
static constexpr int SM_XLO = SM_XHI + 128 * ROWB;
static constexpr int SM_WHI = SM_XLO + 128 * ROWB;
static constexpr int SM_WLO = SM_WHI + 64 * ROWB;
static constexpr int SM_TOTAL = SM_WLO + 64 * ROWB;  // 55296

__device__ __forceinline__ void mma_bf16(float* c, const uint32_t* a,
                                         uint32_t b0, uint32_t b1) {
    asm volatile(
        "mma.sync.aligned.m16n8k16.row.col.f32.bf16.bf16.f32 "
        "{%0,%1,%2,%3}, {%4,%5,%6,%7}, {%8,%9}, {%0,%1,%2,%3};"
        : "+f"(c[0]), "+f"(c[1]), "+f"(c[2]), "+f"(c[3])
        : "r"(a[0]), "r"(a[1]), "r"(a[2]), "r"(a[3]), "r"(b0), "r"(b1));
}
__device__ __forceinline__ uint32_t lds_u32(const char* base, int off) {
    return *(const uint32_t*)(base + off);
}

__device__ __forceinline__ void load_chunk_regs(const float* __restrict__ x,
                                                const float* __restrict__ Wp,
                                                int nodeBase, int kc, int tid,
                                                float4* xv, float4* wv) {
    #pragma unroll
    for (int i = 0; i < 8; i++) {
        int idx = tid + 256 * i;
        int row = idx >> 4, g = idx & 15;
        int node = nodeBase + row;
        xv[i] = (node < N_NODES)
              ? *(const float4*)&x[(size_t)node * D_IN + kc + g * 4]
              : make_float4(0.f, 0.f, 0.f, 0.f);
    }
    #pragma unroll
    for (int i = 0; i < 4; i++) {
        int idx = tid + 256 * i;
        int row = idx >> 4, g = idx & 15;
        wv[i] = *(const float4*)&Wp[(size_t)row * D_IN + kc + g * 4];
    }
}

__device__ __forceinline__ void store_chunk_smem(char* sm, int tid,
                                                 const float4* xv, const float4* wv) {
    #pragma unroll
    for (int i = 0; i < 8; i++) {
        int idx = tid + 256 * i;
        int row = idx >> 4, g = idx & 15;
        float f[4] = {xv[i].x, xv[i].y, xv[i].z, xv[i].w};
        __nv_bfloat16 hi[4], lo[4];
        #pragma unroll
        for (int j = 0; j < 4; j++) {
            hi[j] = __float2bfloat16(f[j]);
            lo[j] = __float2bfloat16(f[j] - __bfloat162float(hi[j]));
        }
        int off = row * ROWB + g * 8;
        *(uint2*)(sm + SM_XHI + off) = *(uint2*)hi;
        *(uint2*)(sm + SM_XLO + off) = *(uint2*)lo;
    }
    #pragma unroll
    for (int i = 0; i < 4; i++) {
        int idx = tid + 256 * i;
        int row = idx >> 4, g = idx & 15;
        float f[4] = {wv[i].x, wv[i].y, wv[i].z, wv[i].w};
        __nv_bfloat16 hi[4], lo[4];
        #pragma unroll
        for (int j = 0; j < 4; j++) {
            hi[j] = __float2bfloat16(f[j]);
            lo[j] = __float2bfloat16(f[j] - __bfloat162float(hi[j]));
        }
        int off = row * ROWB + g * 8;
        *(uint2*)(sm + SM_WHI + off) = *(uint2*)hi;
        *(uint2*)(sm + SM_WLO + off) = *(uint2*)lo;
    }
}

__global__ __launch_bounds__(256) void k_gemm_mma(const float* __restrict__ x,
                                                  const float* __restrict__ Wp) {
    extern __shared__ char sm[];
    const int tid = threadIdx.x;
    const int w   = tid >> 5;
    const int lane = tid & 31;
    const int nodeBase = blockIdx.x * 128;

    float acc[8][4];
    #pragma unroll
    for (int nt = 0; nt < 8; nt++)
        #pragma unroll
        for (int j = 0; j < 4; j++) acc[nt][j] = 0.f;

    float4 xv[8], wv[4];
    load_chunk_regs(x, Wp, nodeBase, 0, tid, xv, wv);
    store_chunk_smem(sm, tid, xv, wv);
    __syncthreads();

    for (int c = 0; c < 4; c++) {
        if (c < 3) load_chunk_regs(x, Wp, nodeBase, (c + 1) * 64, tid, xv, wv);

        #pragma unroll
        for (int ks = 0; ks < 4; ks++) {
            const int kb = ks * 32 + (lane & 3) * 4;
            const int ar = (w * 16 + (lane >> 2)) * ROWB;
            uint32_t ah[4], al[4];
            ah[0] = lds_u32(sm + SM_XHI, ar + kb);
            ah[1] = lds_u32(sm + SM_XHI, ar + 8 * ROWB + kb);
            ah[2] = lds_u32(sm + SM_XHI, ar + kb + 16);
            ah[3] = lds_u32(sm + SM_XHI, ar + 8 * ROWB + kb + 16);
            al[0] = lds_u32(sm + SM_XLO, ar + kb);
            al[1] = lds_u32(sm + SM_XLO, ar + 8 * ROWB + kb);
            al[2] = lds_u32(sm + SM_XLO, ar + kb + 16);
            al[3] = lds_u32(sm + SM_XLO, ar + 8 * ROWB + kb + 16);

            #pragma unroll
            for (int nt = 0; nt < 8; nt++) {
                const int br = (nt * 8 + (lane >> 2)) * ROWB;
                uint32_t bh0 = lds_u32(sm + SM_WHI, br + kb);
                uint32_t bh1 = lds_u32(sm + SM_WHI, br + kb + 16);
                uint32_t bl0 = lds_u32(sm + SM_WLO, br + kb);
                uint32_t bl1 = lds_u32(sm + SM_WLO, br + kb + 16);
                mma_bf16(acc[nt], ah, bh0, bh1);
                mma_bf16(acc[nt], ah, bl0, bl1);
                mma_bf16(acc[nt], al, bh0, bh1);
            }
        }
        __syncthreads();
        if (c < 3) {
            store_chunk_smem(sm, tid, xv, wv);
            __syncthreads();
        }
    }

    const int r0 = nodeBase + w * 16 + (lane >> 2);
    const int r1 = r0 + 8;
    #pragma unroll
    for (int nt = 0; nt < 8; nt++) {
        const int pj = nt * 4 + (lane & 3);
        if (r0 < N_NODES)
            g_yh[(size_t)r0 * 32 + pj] = __floats2half2_rn(acc[nt][0], acc[nt][1]);
        if (r1 < N_NODES)
            g_yh[(size_t)r1 * 32 + pj] = __floats2half2_rn(acc[nt][2], acc[nt][3]);
    }
}

// ---------------------------------------------------------------------------
// Gather: one warp per node, 4 groups x 8 lanes. Each lane holds uint4
// (8 columns); one group = one neighbor row per iteration -> warp retires
// 4 edges/body. Adjacency + dinv via broadcast loads (no shuffles).
// acc = dinv[n]*y[n] + Σ dinv[r]*y[r]; out = fmax(acc*dinv[n]*sc + sh, 0)
// ---------------------------------------------------------------------------
__device__ __forceinline__ void acc_fma(float* acc, uint4 v, float d) {
    float2 f0 = __half22float2(*reinterpret_cast<const __half2*>(&v.x));
    float2 f1 = __half22float2(*reinterpret_cast<const __half2*>(&v.y));
    float2 f2 = __half22float2(*reinterpret_cast<const __half2*>(&v.z));
    float2 f3 = __half22float2(*reinterpret_cast<const __half2*>(&v.w));
    acc[0] = fmaf(d, f0.x, acc[0]); acc[1] = fmaf(d, f0.y, acc[1]);
    acc[2] = fmaf(d, f1.x, acc[2]); acc[3] = fmaf(d, f1.y, acc[3]);
    acc[4] = fmaf(d, f2.x, acc[4]); acc[5] = fmaf(d, f2.y, acc[5]);
    acc[6] = fmaf(d, f3.x, acc[6]); acc[7] = fmaf(d, f3.y, acc[7]);
}

__global__ __launch_bounds__(256) void k_gather(float* __restrict__ out) {
    const int warp = (blockIdx.x * blockDim.x + threadIdx.x) >> 5;
    const int lane = threadIdx.x & 31;
    if (warp >= N_NODES) return;
    const int node = warp;
    const int lq = lane & 7;    // column quad: bytes [lq*16, lq*16+16) of a row
    const int lg = lane >> 3;   // group 0..3

    const char* ybase = (const char*)g_yh + lq * 16;
    const float di = g_dinv[node];

    float acc[8] = {0.f, 0.f, 0.f, 0.f, 0.f, 0.f, 0.f, 0.f};

    if (lg == 0)   // self term
        acc_fma(acc, *(const uint4*)(ybase + (size_t)node * ROWBYTES), di);

    const int deg   = g_cur[node];
    const int trips = ((deg + 3) & ~3) >> 2;   // degp/4, padded slots -> ZOFF
    const int* ap = g_adj + (size_t)node * CAP + lg;

    #pragma unroll 4
    for (int t = 0; t < trips; t++) {
        int off = ap[4 * t];                  // 8-lane broadcast (4 addrs/warp)
        float d = g_dinv[off >> 7];           // 0 for pad rows
        uint4 v = *(const uint4*)(ybase + off);
        acc_fma(acc, v, d);
    }

    // reduce across the 4 groups (lanes lq, lq+8, lq+16, lq+24)
    #pragma unroll
    for (int t = 0; t < 8; t++) {
        acc[t] += __shfl_xor_sync(0xffffffffu, acc[t], 8);
        acc[t] += __shfl_xor_sync(0xffffffffu, acc[t], 16);
    }

    if (lg == 0) {
        const int c0 = lq * 8;
        float4 sc0 = *(const float4*)&g_sc[c0];
        float4 sc1 = *(const float4*)&g_sc[c0 + 4];
        float4 sh0 = *(const float4*)&g_sh[c0];
        float4 sh1 = *(const float4*)&g_sh[c0 + 4];
        float4 o0, o1;
        o0.x = fmaxf(fmaf(acc[0] * di, sc0.x, sh0.x), 0.f);
        o0.y = fmaxf(fmaf(acc[1] * di, sc0.y, sh0.y), 0.f);
        o0.z = fmaxf(fmaf(acc[2] * di, sc0.z, sh0.z), 0.f);
        o0.w = fmaxf(fmaf(acc[3] * di, sc0.w, sh0.w), 0.f);
        o1.x = fmaxf(fmaf(acc[4] * di, sc1.x, sh1.x), 0.f);
        o1.y = fmaxf(fmaf(acc[5] * di, sc1.y, sh1.y), 0.f);
        o1.z = fmaxf(fmaf(acc[6] * di, sc1.z, sh1.z), 0.f);
        o1.w = fmaxf(fmaf(acc[7] * di, sc1.w, sh1.w), 0.f);
        *(float4*)&out[(size_t)node * D_OUT + c0]     = o0;
        *(float4*)&out[(size_t)node * D_OUT + c0 + 4] = o1;
    }
}

// ---------------------------------------------------------------------------
extern "C" void kernel_launch(void* const* d_in, const int* in_sizes, int n_in,
                              void* d_out, int out_size) {
    const float* x     = (const float*)d_in[0];
    const int*   ei    = (const int*)  d_in[1];
    const float* W     = (const float*)d_in[2];
    const float* bias  = (const float*)d_in[3];
    const float* gamma = (const float*)d_in[4];
    const float* beta  = (const float*)d_in[5];
    const float* mean  = (const float*)d_in[6];
    const float* var   = (const float*)d_in[7];
    float* out = (float*)d_out;

    const int4* rows4 = (const int4*)ei;              // edge_index[0] = source
    const int4* cols4 = (const int4*)(ei + N_EDGES);  // edge_index[1] = target

    static cudaStream_t s2 = nullptr;
    static cudaEvent_t evFork = nullptr, evJoin = nullptr;
    static void* cur_addr = nullptr;
    if (!s2) {
        cudaStreamCreateWithFlags(&s2, cudaStreamNonBlocking);
        cudaEventCreateWithFlags(&evFork, cudaEventDisableTiming);
        cudaEventCreateWithFlags(&evJoin, cudaEventDisableTiming);
        cudaGetSymbolAddress(&cur_addr, g_cur);
        cudaFuncSetAttribute(k_gemm_mma, cudaFuncAttributeMaxDynamicSharedMemorySize, SM_TOTAL);
    }

    // fork: graph build on s2; GEMM (independent) on main
    cudaEventRecord(evFork, 0);
    cudaStreamWaitEvent(s2, evFork, 0);

    cudaMemsetAsync(cur_addr, 0, N_NODES * sizeof(int), s2);
    k_fill4  <<<(N_EDGES / 4 + 255) / 256, 256, 0, s2>>>(rows4, cols4);
    k_dinvpad<<<(N_NODES + 255) / 256, 256, 0, s2>>>();
    k_prep   <<<1, 64, 0, s2>>>(bias, gamma, beta, mean, var);

    k_gemm_mma<<<(N_NODES + 127) / 128, 256, SM_TOTAL>>>(x, W);

    // join
    cudaEventRecord(evJoin, s2);
    cudaStreamWaitEvent(0, evJoin, 0);

    k_gather<<<(N_NODES * 32 + 255) / 256, 256>>>(out);
}

// round 17
// speedup vs baseline: 1.3754x; 1.1362x over previous
#include <cuda_runtime.h>
#include <cuda_bf16.h>
#include <cuda_fp16.h>
#include <cstdint>

#define N_NODES 100000
#define N_EDGES 1600000
#define D_IN    256
#define D_OUT   64
#define BN_EPS  1e-5f
#define CAP     88      // 80 (Poisson(16) bound) + 3 padding slots
#define ROWBYTES 128    // one y row = 64 half = 128 B
#define ZOFF    (N_NODES * ROWBYTES)   // byte offset of the zero row

// Scratch (device globals — no allocation allowed)
__device__ __half2 g_yh[((size_t)N_NODES + 1) * 32];  // UNscaled x W^T + zero row
__device__ int     g_cur[N_NODES];                    // fill cursors -> degrees
__device__ float   g_dinv[N_NODES + 1];               // [N_NODES] = 0 (pad slot)
__device__ int     g_adj[(size_t)N_NODES * CAP];      // BYTE OFFSETS of source rows
__device__ float   g_sc[D_OUT];                       // rsqrt(var+eps)*gamma
__device__ float   g_sh[D_OUT];                       // (bias-mean)*sc + beta

// ---------------------------------------------------------------------------
// s2 branch: adjacency fill (byte offsets); degrees = final cursors;
// dinv + pad-to-x4 + zero row; BN constant folding.
// ---------------------------------------------------------------------------
__global__ __launch_bounds__(256) void k_fill4(const int4* __restrict__ rows4,
                                               const int4* __restrict__ cols4) {
    int i = blockIdx.x * blockDim.x + threadIdx.x;
    if (i < N_EDGES / 4) {
        int4 r = rows4[i];
        int4 c = cols4[i];
        int p0 = atomicAdd(&g_cur[c.x], 1);
        int p1 = atomicAdd(&g_cur[c.y], 1);
        int p2 = atomicAdd(&g_cur[c.z], 1);
        int p3 = atomicAdd(&g_cur[c.w], 1);
        g_adj[(size_t)c.x * CAP + p0] = r.x << 7;   // byte offset = r * 128
        g_adj[(size_t)c.y * CAP + p1] = r.y << 7;
        g_adj[(size_t)c.z * CAP + p2] = r.z << 7;
        g_adj[(size_t)c.w * CAP + p3] = r.w << 7;
    }
}
__global__ void k_dinvpad() {
    int i = blockIdx.x * blockDim.x + threadIdx.x;
    if (i < 32) g_yh[(size_t)N_NODES * 32 + i] = __floats2half2_rn(0.f, 0.f);
    if (i == 0) g_dinv[N_NODES] = 0.f;               // pad rows contribute 0
    if (i < N_NODES) {
        int d = g_cur[i];
        g_dinv[i] = rsqrtf((float)(d + 1));          // +1 self-loop
        int degp = (d + 3) & ~3;
        #pragma unroll
        for (int p = 0; p < 3; p++)
            if (d + p < degp) g_adj[(size_t)i * CAP + d + p] = ZOFF;
    }
}
__global__ void k_prep(const float* __restrict__ bias,
                       const float* __restrict__ gamma,
                       const float* __restrict__ beta,
                       const float* __restrict__ mean,
                       const float* __restrict__ var) {
    int d = threadIdx.x;
    if (d < D_OUT) {
        float sc = rsqrtf(var[d] + BN_EPS) * gamma[d];
        g_sc[d] = sc;
        g_sh[d] = (bias[d] - mean[d]) * sc + beta[d];
    }
}

// ---------------------------------------------------------------------------
// Tensor-core GEMM via mma.sync, SINGLE-PASS fp16 (f32.f16.f16.f32),
// software-pipelined with register staging. Stores UNscaled half2 y.
// CTA: 128 nodes x 64 douts, 256 threads. K chunked by 64.
// ---------------------------------------------------------------------------
#define ROWB 144   // 64 halfs (128B) padded to 144B: frag LDS conflict-free
static constexpr int SM_X = 0;                        // 128 rows x ROWB
static constexpr int SM_W = 128 * ROWB;               // 64 rows x ROWB
static constexpr int SM_TOTAL = SM_W + 64 * ROWB;     // 27648 B

__device__ __forceinline__ void mma_f16(float* c, const uint32_t* a,
                                        uint32_t b0, uint32_t b1) {
    asm volatile(
        "mma.sync.aligned.m16n8k16.row.col.f32.f16.f16.f32 "
        "{%0,%1,%2,%3}, {%4,%5,%6,%7}, {%8,%9}, {%0,%1,%2,%3};"
        : "+f"(c[0]), "+f"(c[1]), "+f"(c[2]), "+f"(c[3])
        : "r"(a[0]), "r"(a[1]), "r"(a[2]), "r"(a[3]), "r"(b0), "r"(b1));
}
__device__ __forceinline__ uint32_t lds_u32(const char* base, int off) {
    return *(const uint32_t*)(base + off);
}

__device__ __forceinline__ void load_chunk_regs(const float* __restrict__ x,
                                                const float* __restrict__ Wp,
                                                int nodeBase, int kc, int tid,
                                                float4* xv, float4* wv) {
    #pragma unroll
    for (int i = 0; i < 8; i++) {
        int idx = tid + 256 * i;
        int row = idx >> 4, g = idx & 15;
        int node = nodeBase + row;
        xv[i] = (node < N_NODES)
              ? *(const float4*)&x[(size_t)node * D_IN + kc + g * 4]
              : make_float4(0.f, 0.f, 0.f, 0.f);
    }
    #pragma unroll
    for (int i = 0; i < 4; i++) {
        int idx = tid + 256 * i;
        int row = idx >> 4, g = idx & 15;
        wv[i] = *(const float4*)&Wp[(size_t)row * D_IN + kc + g * 4];
    }
}

__device__ __forceinline__ void store_chunk_smem(char* sm, int tid,
                                                 const float4* xv, const float4* wv) {
    #pragma unroll
    for (int i = 0; i < 8; i++) {
        int idx = tid + 256 * i;
        int row = idx >> 4, g = idx & 15;
        uint2 h;
        *(__half2*)&h.x = __floats2half2_rn(xv[i].x, xv[i].y);
        *(__half2*)&h.y = __floats2half2_rn(xv[i].z, xv[i].w);
        *(uint2*)(sm + SM_X + row * ROWB + g * 8) = h;
    }
    #pragma unroll
    for (int i = 0; i < 4; i++) {
        int idx = tid + 256 * i;
        int row = idx >> 4, g = idx & 15;
        uint2 h;
        *(__half2*)&h.x = __floats2half2_rn(wv[i].x, wv[i].y);
        *(__half2*)&h.y = __floats2half2_rn(wv[i].z, wv[i].w);
        *(uint2*)(sm + SM_W + row * ROWB + g * 8) = h;
    }
}

__global__ __launch_bounds__(256) void k_gemm_mma(const float* __restrict__ x,
                                                  const float* __restrict__ Wp) {
    extern __shared__ char sm[];
    const int tid = threadIdx.x;
    const int w   = tid >> 5;
    const int lane = tid & 31;
    const int nodeBase = blockIdx.x * 128;

    float acc[8][4];
    #pragma unroll
    for (int nt = 0; nt < 8; nt++)
        #pragma unroll
        for (int j = 0; j < 4; j++) acc[nt][j] = 0.f;

    float4 xv[8], wv[4];
    load_chunk_regs(x, Wp, nodeBase, 0, tid, xv, wv);
    store_chunk_smem(sm, tid, xv, wv);
    __syncthreads();

    for (int c = 0; c < 4; c++) {
        if (c < 3) load_chunk_regs(x, Wp, nodeBase, (c + 1) * 64, tid, xv, wv);

        #pragma unroll
        for (int ks = 0; ks < 4; ks++) {
            const int kb = ks * 32 + (lane & 3) * 4;
            const int ar = (w * 16 + (lane >> 2)) * ROWB;
            uint32_t a[4];
            a[0] = lds_u32(sm + SM_X, ar + kb);
            a[1] = lds_u32(sm + SM_X, ar + 8 * ROWB + kb);
            a[2] = lds_u32(sm + SM_X, ar + kb + 16);
            a[3] = lds_u32(sm + SM_X, ar + 8 * ROWB + kb + 16);

            #pragma unroll
            for (int nt = 0; nt < 8; nt++) {
                const int br = (nt * 8 + (lane >> 2)) * ROWB;
                uint32_t b0 = lds_u32(sm + SM_W, br + kb);
                uint32_t b1 = lds_u32(sm + SM_W, br + kb + 16);
                mma_f16(acc[nt], a, b0, b1);
            }
        }
        __syncthreads();
        if (c < 3) {
            store_chunk_smem(sm, tid, xv, wv);
            __syncthreads();
        }
    }

    // store UNscaled half2: col pair (nt*8 + (lane&3)*2, +1) -> pair idx nt*4+(lane&3)
    const int r0 = nodeBase + w * 16 + (lane >> 2);
    const int r1 = r0 + 8;
    #pragma unroll
    for (int nt = 0; nt < 8; nt++) {
        const int pj = nt * 4 + (lane & 3);
        if (r0 < N_NODES)
            g_yh[(size_t)r0 * 32 + pj] = __floats2half2_rn(acc[nt][0], acc[nt][1]);
        if (r1 < N_NODES)
            g_yh[(size_t)r1 * 32 + pj] = __floats2half2_rn(acc[nt][2], acc[nt][3]);
    }
}

// ---------------------------------------------------------------------------
// Gather: one warp per node, 4 groups x 8 lanes. Each lane holds uint4
// (8 columns); one group = one neighbor row per iteration -> warp retires
// 4 edges/body. Adjacency + dinv via broadcast loads (no shuffles).
// acc = dinv[n]*y[n] + Σ dinv[r]*y[r]; out = fmax(acc*dinv[n]*sc + sh, 0)
// ---------------------------------------------------------------------------
__device__ __forceinline__ void acc_fma(float* acc, uint4 v, float d) {
    float2 f0 = __half22float2(*reinterpret_cast<const __half2*>(&v.x));
    float2 f1 = __half22float2(*reinterpret_cast<const __half2*>(&v.y));
    float2 f2 = __half22float2(*reinterpret_cast<const __half2*>(&v.z));
    float2 f3 = __half22float2(*reinterpret_cast<const __half2*>(&v.w));
    acc[0] = fmaf(d, f0.x, acc[0]); acc[1] = fmaf(d, f0.y, acc[1]);
    acc[2] = fmaf(d, f1.x, acc[2]); acc[3] = fmaf(d, f1.y, acc[3]);
    acc[4] = fmaf(d, f2.x, acc[4]); acc[5] = fmaf(d, f2.y, acc[5]);
    acc[6] = fmaf(d, f3.x, acc[6]); acc[7] = fmaf(d, f3.y, acc[7]);
}

__global__ __launch_bounds__(256) void k_gather(float* __restrict__ out) {
    const int warp = (blockIdx.x * blockDim.x + threadIdx.x) >> 5;
    const int lane = threadIdx.x & 31;
    if (warp >= N_NODES) return;
    const int node = warp;
    const int lq = lane & 7;    // column quad: bytes [lq*16, lq*16+16) of a row
    const int lg = lane >> 3;   // group 0..3

    const char* ybase = (const char*)g_yh + lq * 16;
    const float di = g_dinv[node];

    float acc[8] = {0.f, 0.f, 0.f, 0.f, 0.f, 0.f, 0.f, 0.f};

    if (lg == 0)   // self term
        acc_fma(acc, *(const uint4*)(ybase + (size_t)node * ROWBYTES), di);

    const int deg   = g_cur[node];
    const int trips = ((deg + 3) & ~3) >> 2;   // degp/4, padded slots -> ZOFF
    const int* ap = g_adj + (size_t)node * CAP + lg;

    #pragma unroll 4
    for (int t = 0; t < trips; t++) {
        int off = ap[4 * t];                  // 8-lane broadcast (4 addrs/warp)
        float d = g_dinv[off >> 7];           // 0 for pad rows
        uint4 v = *(const uint4*)(ybase + off);
        acc_fma(acc, v, d);
    }

    // reduce across the 4 groups (lanes lq, lq+8, lq+16, lq+24)
    #pragma unroll
    for (int t = 0; t < 8; t++) {
        acc[t] += __shfl_xor_sync(0xffffffffu, acc[t], 8);
        acc[t] += __shfl_xor_sync(0xffffffffu, acc[t], 16);
    }

    if (lg == 0) {
        const int c0 = lq * 8;
        float4 sc0 = *(const float4*)&g_sc[c0];
        float4 sc1 = *(const float4*)&g_sc[c0 + 4];
        float4 sh0 = *(const float4*)&g_sh[c0];
        float4 sh1 = *(const float4*)&g_sh[c0 + 4];
        float4 o0, o1;
        o0.x = fmaxf(fmaf(acc[0] * di, sc0.x, sh0.x), 0.f);
        o0.y = fmaxf(fmaf(acc[1] * di, sc0.y, sh0.y), 0.f);
        o0.z = fmaxf(fmaf(acc[2] * di, sc0.z, sh0.z), 0.f);
        o0.w = fmaxf(fmaf(acc[3] * di, sc0.w, sh0.w), 0.f);
        o1.x = fmaxf(fmaf(acc[4] * di, sc1.x, sh1.x), 0.f);
        o1.y = fmaxf(fmaf(acc[5] * di, sc1.y, sh1.y), 0.f);
        o1.z = fmaxf(fmaf(acc[6] * di, sc1.z, sh1.z), 0.f);
        o1.w = fmaxf(fmaf(acc[7] * di, sc1.w, sh1.w), 0.f);
        *(float4*)&out[(size_t)node * D_OUT + c0]     = o0;
        *(float4*)&out[(size_t)node * D_OUT + c0 + 4] = o1;
    }
}

// ---------------------------------------------------------------------------
extern "C" void kernel_launch(void* const* d_in, const int* in_sizes, int n_in,
                              void* d_out, int out_size) {
    const float* x     = (const float*)d_in[0];
    const int*   ei    = (const int*)  d_in[1];
    const float* W     = (const float*)d_in[2];
    const float* bias  = (const float*)d_in[3];
    const float* gamma = (const float*)d_in[4];
    const float* beta  = (const float*)d_in[5];
    const float* mean  = (const float*)d_in[6];
    const float* var   = (const float*)d_in[7];
    float* out = (float*)d_out;

    const int4* rows4 = (const int4*)ei;              // edge_index[0] = source
    const int4* cols4 = (const int4*)(ei + N_EDGES);  // edge_index[1] = target

    static cudaStream_t s2 = nullptr;
    static cudaEvent_t evFork = nullptr, evJoin = nullptr;
    static void* cur_addr = nullptr;
    if (!s2) {
        cudaStreamCreateWithFlags(&s2, cudaStreamNonBlocking);
        cudaEventCreateWithFlags(&evFork, cudaEventDisableTiming);
        cudaEventCreateWithFlags(&evJoin, cudaEventDisableTiming);
        cudaGetSymbolAddress(&cur_addr, g_cur);
        cudaFuncSetAttribute(k_gemm_mma, cudaFuncAttributeMaxDynamicSharedMemorySize, SM_TOTAL);
    }

    // fork: graph build on s2; GEMM (independent) on main
    cudaEventRecord(evFork, 0);
    cudaStreamWaitEvent(s2, evFork, 0);

    cudaMemsetAsync(cur_addr, 0, N_NODES * sizeof(int), s2);
    k_fill4  <<<(N_EDGES / 4 + 255) / 256, 256, 0, s2>>>(rows4, cols4);
    k_dinvpad<<<(N_NODES + 255) / 256, 256, 0, s2>>>();
    k_prep   <<<1, 64, 0, s2>>>(bias, gamma, beta, mean, var);

    k_gemm_mma<<<(N_NODES + 127) / 128, 256, SM_TOTAL>>>(x, W);

    // join
    cudaEventRecord(evJoin, s2);
    cudaStreamWaitEvent(0, evJoin, 0);

    k_gather<<<(N_NODES * 32 + 255) / 256, 256>>>(out);
}